// round 1
// baseline (speedup 1.0000x reference)
#include <cuda_runtime.h>

// Problem constants: N=2048, D=128, k=4 augs, TEMPERATURE=0.5
// rows (queries)  : 4096 = 2N
// cols (keys)     : 8192 = kN
#define D 128

// Scratch (device globals: no allocation allowed)
__device__ float g_norm[8192 * 128];   // normalized z_all, row-major
__device__ float g_S[4 * 4096];        // partial sum-of-exp per (chunk,row)
__device__ float g_pos[4 * 4096];      // partial positive logit per (chunk,row)

typedef unsigned long long u64;

__device__ __forceinline__ u64 fma2(u64 a, u64 b, u64 c) {
    u64 d;
    asm("fma.rn.f32x2 %0, %1, %2, %3;" : "=l"(d) : "l"(a), "l"(b), "l"(c));
    return d;
}
__device__ __forceinline__ u64 pack_dup(float x) {
    u64 r;
    asm("mov.b64 %0, {%1, %1};" : "=l"(r) : "f"(x));
    return r;
}
__device__ __forceinline__ float2 unpack2(u64 v) {
    float2 f;
    asm("mov.b64 {%0, %1}, %2;" : "=f"(f.x), "=f"(f.y) : "l"(v));
    return f;
}

// ---------------------------------------------------------------------------
// Kernel 1: L2-normalize all 8192 rows into g_norm. One warp per row.
// ---------------------------------------------------------------------------
__global__ void normalize_kernel(const float* __restrict__ a1,
                                 const float* __restrict__ a2,
                                 const float* __restrict__ a3,
                                 const float* __restrict__ a4) {
    int w = threadIdx.x >> 5, lane = threadIdx.x & 31;
    int row = blockIdx.x * 8 + w;  // 0..8191
    const float* src = (row < 2048) ? a1 : (row < 4096) ? a2
                      : (row < 6144) ? a3 : a4;
    int r = row & 2047;
    float4 v = *(const float4*)(src + r * D + lane * 4);
    float ss = v.x * v.x + v.y * v.y + v.z * v.z + v.w * v.w;
#pragma unroll
    for (int off = 16; off; off >>= 1) ss += __shfl_xor_sync(~0u, ss, off);
    float n = sqrtf(ss);
    float inv = 1.0f / fmaxf(n, 1e-8f);
    v.x *= inv; v.y *= inv; v.z *= inv; v.w *= inv;
    *(float4*)(&g_norm[row * D + lane * 4]) = v;
}

// ---------------------------------------------------------------------------
// Kernel 2: tiled sim GEMM + masked exp-sum epilogue.
// Block: 256 threads (8 warps). Block tile: 32 rows x 4096 cols (grid.y=2 col
// splits). Inner col tile: 128 cols. Warp w: rows (w&3)*8..+8, col half w>>2.
// Thread micro-tile: 8 rows x 2 cols via fma.rn.f32x2 (FFMA2).
// SMEM: As [128k][36] (k-major, pad 4), Bs [128k][132] (k-major, pad 4).
// ---------------------------------------------------------------------------
#define AS_STRIDE 36
#define BS_STRIDE 132
#define SMEM_BYTES (128 * AS_STRIDE * 4 + 128 * BS_STRIDE * 4)

__global__ void sim_kernel() {
    extern __shared__ float sm[];
    float* As = sm;                       // [128][36]
    float* Bs = sm + 128 * AS_STRIDE;     // [128][132]

    int tid = threadIdx.x;
    int w = tid >> 5, lane = tid & 31;
    int row0 = blockIdx.x * 32;           // 128 row tiles
    int cs = blockIdx.y;                  // 2 col splits of 4096 cols each

    // Load A tile (32 rows x 128) transposed to k-major
    for (int idx = tid; idx < 32 * 128; idx += 256) {
        int r = idx >> 7, k = idx & 127;
        As[k * AS_STRIDE + r] = g_norm[(row0 + r) * D + k];
    }

    int rg = (w & 3) * 8;   // warp's first row within tile
    int ch = w >> 2;        // 0/1: which 64-col half of the 128-col tile

    float expSum[8], posSum[8];
#pragma unroll
    for (int i = 0; i < 8; i++) { expSum[i] = 0.f; posSum[i] = 0.f; }

    for (int ct = 0; ct < 32; ct++) {
        int col0 = cs * 4096 + ct * 128;
        __syncthreads();  // previous tile compute done (also covers As on ct=0)
        for (int idx = tid; idx < 128 * 128; idx += 256) {
            int c = idx >> 7, k = idx & 127;
            Bs[k * BS_STRIDE + c] = g_norm[(col0 + c) * D + k];
        }
        __syncthreads();

        u64 acc[4][2];
#pragma unroll
        for (int p = 0; p < 4; p++) { acc[p][0] = 0ull; acc[p][1] = 0ull; }

        const float* ap = As + rg;
        const float* bp = Bs + ch * 64 + lane * 2;
#pragma unroll 16
        for (int k = 0; k < 128; k++) {
            ulonglong2 alo = *(const ulonglong2*)(ap + k * AS_STRIDE);      // rows rg..rg+3
            ulonglong2 ahi = *(const ulonglong2*)(ap + k * AS_STRIDE + 4);  // rows rg+4..rg+7
            float2 b = *(const float2*)(bp + k * BS_STRIDE);
            u64 b0 = pack_dup(b.x);
            u64 b1 = pack_dup(b.y);
            acc[0][0] = fma2(alo.x, b0, acc[0][0]);
            acc[0][1] = fma2(alo.x, b1, acc[0][1]);
            acc[1][0] = fma2(alo.y, b0, acc[1][0]);
            acc[1][1] = fma2(alo.y, b1, acc[1][1]);
            acc[2][0] = fma2(ahi.x, b0, acc[2][0]);
            acc[2][1] = fma2(ahi.x, b1, acc[2][1]);
            acc[3][0] = fma2(ahi.y, b0, acc[3][0]);
            acc[3][1] = fma2(ahi.y, b1, acc[3][1]);
        }

        // Epilogue: scale by 1/T=2, mask, exp, accumulate. Masked entries
        // (diag of non-target block) contribute 0 (exp(-1e30)); logits are
        // bounded in [-2,2] so no max-subtraction is needed.
#pragma unroll
        for (int p = 0; p < 4; p++) {
#pragma unroll
            for (int cc = 0; cc < 2; cc++) {
                float2 s = unpack2(acc[p][cc]);
                int col = col0 + ch * 64 + lane * 2 + cc;
                int cidx = col & 2047;
                int cblk = col >> 11;
#pragma unroll
                for (int q = 0; q < 2; q++) {
                    float simv = (q ? s.y : s.x) * 2.0f;
                    int row = row0 + rg + 2 * p + q;
                    int ridx = row & 2047;
                    int half = row >> 11;
                    bool diag = (cidx == ridx);
                    bool tgt = (cblk == (1 - half));
                    float e = __expf(simv);
                    if (diag && !tgt) e = 0.f;          // masked
                    expSum[2 * p + q] += e;
                    if (diag && tgt) posSum[2 * p + q] += simv;  // positive
                }
            }
        }
    }

    // Warp-reduce over the 32 lanes (cols); lane 0 owns one (chunk,row) slot.
#pragma unroll
    for (int rr = 0; rr < 8; rr++) {
        float e = expSum[rr], p = posSum[rr];
#pragma unroll
        for (int off = 16; off; off >>= 1) {
            e += __shfl_xor_sync(~0u, e, off);
            p += __shfl_xor_sync(~0u, p, off);
        }
        if (lane == 0) {
            int chunk = cs * 2 + ch;         // 0..3, each row written once/chunk
            int row = row0 + rg + rr;
            g_S[chunk * 4096 + row] = e;
            g_pos[chunk * 4096 + row] = p;
        }
    }
}

// ---------------------------------------------------------------------------
// Kernel 3: loss = mean over 4096 rows of log(sum_exp) - pos.
// ---------------------------------------------------------------------------
__global__ void finalize_kernel(float* __restrict__ out) {
    __shared__ float red[256];
    int tid = threadIdx.x;
    float local = 0.f;
    for (int row = tid; row < 4096; row += 256) {
        float S = g_S[row] + g_S[4096 + row] + g_S[8192 + row] + g_S[12288 + row];
        float p = g_pos[row] + g_pos[4096 + row] + g_pos[8192 + row] + g_pos[12288 + row];
        local += logf(S) - p;
    }
    red[tid] = local;
    __syncthreads();
#pragma unroll
    for (int s = 128; s; s >>= 1) {
        if (tid < s) red[tid] += red[tid + s];
        __syncthreads();
    }
    if (tid == 0) out[0] = red[0] / 4096.f;
}

// ---------------------------------------------------------------------------
extern "C" void kernel_launch(void* const* d_in, const int* in_sizes, int n_in,
                              void* d_out, int out_size) {
    const float* a1 = (const float*)d_in[0];
    const float* a2 = (const float*)d_in[1];
    const float* a3 = (const float*)d_in[2];
    const float* a4 = (const float*)d_in[3];

    normalize_kernel<<<1024, 256>>>(a1, a2, a3, a4);

    cudaFuncSetAttribute(sim_kernel, cudaFuncAttributeMaxDynamicSharedMemorySize,
                         SMEM_BYTES);
    dim3 grid(128, 2);
    sim_kernel<<<grid, 256, SMEM_BYTES>>>();

    finalize_kernel<<<1, 256>>>((float*)d_out);
}

// round 3
// speedup vs baseline: 5.9518x; 5.9518x over previous
#include <cuda_runtime.h>
#include <cuda_bf16.h>
#include <cstdint>

// Problem: N=2048, D=128, k=4, T=0.5.
// queries rows = 4096, keys cols = 8192.
// sim = norm(z[0:4096]) @ norm(z_all)^T * 2 ; mask non-target diagonals;
// loss = mean(logsumexp - pos). Logits bounded in [-2,2] -> no max needed;
// masked entries contribute exp(-inf)=0 so we just zero them.

#define DIMK 128

// ---------------- device scratch (no allocations allowed) -------------------
__device__ __nv_bfloat16 g_nb[8192 * 128];  // normalized rows, bf16
__device__ float g_S[64 * 4096];            // per (coltile,row) exp-sum
__device__ float g_pos[64 * 4096];          // per (coltile,row) positive logit

__device__ __forceinline__ uint32_t smem_u32(const void* p) {
    uint32_t a;
    asm("{ .reg .u64 t; cvta.to.shared.u64 t, %1; cvt.u32.u64 %0, t; }"
        : "=r"(a) : "l"(p));
    return a;
}

__device__ __forceinline__ void ldsm_x4(uint32_t* r, uint32_t addr) {
    asm volatile("ldmatrix.sync.aligned.m8n8.x4.shared.b16 {%0,%1,%2,%3}, [%4];"
                 : "=r"(r[0]), "=r"(r[1]), "=r"(r[2]), "=r"(r[3]) : "r"(addr));
}

__device__ __forceinline__ void mma16816(float* c, const uint32_t* a,
                                         uint32_t b0, uint32_t b1) {
    asm volatile(
        "mma.sync.aligned.m16n8k16.row.col.f32.bf16.bf16.f32 "
        "{%0,%1,%2,%3}, {%4,%5,%6,%7}, {%8,%9}, {%0,%1,%2,%3};"
        : "+f"(c[0]), "+f"(c[1]), "+f"(c[2]), "+f"(c[3])
        : "r"(a[0]), "r"(a[1]), "r"(a[2]), "r"(a[3]), "r"(b0), "r"(b1));
}

// ---------------------------------------------------------------------------
// Kernel 1: L2-normalize 8192 rows -> bf16. One warp per row.
// ---------------------------------------------------------------------------
__global__ void normalize_kernel(const float* __restrict__ a1,
                                 const float* __restrict__ a2,
                                 const float* __restrict__ a3,
                                 const float* __restrict__ a4) {
    int w = threadIdx.x >> 5, lane = threadIdx.x & 31;
    int row = blockIdx.x * 8 + w;
    const float* src = (row < 2048) ? a1 : (row < 4096) ? a2
                      : (row < 6144) ? a3 : a4;
    int r = row & 2047;
    float4 v = *(const float4*)(src + r * DIMK + lane * 4);
    float ss = v.x * v.x + v.y * v.y + v.z * v.z + v.w * v.w;
#pragma unroll
    for (int off = 16; off; off >>= 1) ss += __shfl_xor_sync(~0u, ss, off);
    float inv = 1.0f / fmaxf(sqrtf(ss), 1e-8f);
    __nv_bfloat162 p0 = __float22bfloat162_rn(make_float2(v.x * inv, v.y * inv));
    __nv_bfloat162 p1 = __float22bfloat162_rn(make_float2(v.z * inv, v.w * inv));
    uint2 st;
    st.x = *(uint32_t*)&p0;
    st.y = *(uint32_t*)&p1;
    ((uint2*)(g_nb + row * DIMK))[lane] = st;
}

// ---------------------------------------------------------------------------
// Kernel 2: HMMA bf16 GEMM tile (128 rows x 128 cols, K=128) + fused masked
// exp epilogue. 256 threads = 8 warps: warp grid 4(M) x 2(N); warp tile 32x64.
// SMEM tiles with padded stride 272B (136 bf16) for conflict-free ldmatrix.
// grid = (32 row tiles, 64 col tiles).
// ---------------------------------------------------------------------------
#define TSTRIDE 272                     // bytes per SMEM tile row (128 bf16 + 8 pad)
#define SM_A 0
#define SM_B (128 * TSTRIDE)            // 34816
#define SM_S (2 * 128 * TSTRIDE)        // 69632: float sS[2][128]
#define SM_P (SM_S + 1024)              // float sP[2][128]
#define SMEM_BYTES (SM_P + 1024)

__global__ void __launch_bounds__(256, 2) sim_kernel() {
    extern __shared__ char smem[];
    uint32_t sb = smem_u32(smem);
    float* sS = (float*)(smem + SM_S);
    float* sP = (float*)(smem + SM_P);

    int tid = threadIdx.x;
    int lane = tid & 31;
    int w = tid >> 5;
    int wm = w & 3;        // M warp (rows wm*32..+31)
    int wn = w >> 2;       // N warp (cols wn*64..+63)
    int row0 = blockIdx.x * 128;
    int cs = blockIdx.y;                 // col tile: [cs*128, cs*128+128)
    int col0 = cs * 128;
    int cblk = cs >> 4;                  // which 2048-block (tile never straddles)

    // ---- load A tile (rows) and B tile (cols) into padded SMEM ----
#pragma unroll
    for (int it = 0; it < 8; it++) {
        int idx = it * 256 + tid;        // 2048 16B-vectors per tile
        int r = idx >> 4, g = idx & 15;
        uint4 da = *(const uint4*)(g_nb + (row0 + r) * DIMK + g * 8);
        *(uint4*)(smem + SM_A + r * TSTRIDE + g * 16) = da;
        uint4 db = *(const uint4*)(g_nb + (col0 + r) * DIMK + g * 8);
        *(uint4*)(smem + SM_B + r * TSTRIDE + g * 16) = db;
    }
    __syncthreads();

    // ---- ldmatrix lane address bases ----
    // A x4 (m16k16): lanes 0-7 rows m0-7 (k lo octet), 8-15 rows m8-15,
    //                16-23 rows m0-7 (k hi octet), 24-31 rows m8-15 (k hi).
    int arow = wm * 32 + ((lane >> 3) & 1) * 8 + (lane & 7);
    int akoct = (lane >> 4) * 8;
    uint32_t baseA = sb + SM_A + arow * TSTRIDE + akoct * 2;
    // B x4 (two n8 tiles of k16): lanes 0-7 rows n0-7 (k lo), 8-15 rows n0-7
    //                (k hi), 16-23 rows n8-15 (k lo), 24-31 rows n8-15 (k hi).
    int brow = wn * 64 + ((lane >> 4) & 1) * 8 + (lane & 7);
    int bkoct = ((lane >> 3) & 1) * 8;
    uint32_t baseB = sb + SM_B + brow * TSTRIDE + bkoct * 2;

    float acc[2][8][4];
#pragma unroll
    for (int mi = 0; mi < 2; mi++)
#pragma unroll
        for (int ni = 0; ni < 8; ni++)
#pragma unroll
            for (int c = 0; c < 4; c++) acc[mi][ni][c] = 0.f;

    // ---- K loop: 8 k-steps of 16 ----
#pragma unroll
    for (int ks = 0; ks < 8; ks++) {
        uint32_t a[2][4];
        ldsm_x4(a[0], baseA + ks * 32);
        ldsm_x4(a[1], baseA + 16 * TSTRIDE + ks * 32);
        uint32_t b[4][4];
#pragma unroll
        for (int nip = 0; nip < 4; nip++)
            ldsm_x4(b[nip], baseB + nip * 16 * TSTRIDE + ks * 32);
#pragma unroll
        for (int mi = 0; mi < 2; mi++)
#pragma unroll
            for (int nip = 0; nip < 4; nip++) {
                mma16816(acc[mi][2 * nip + 0], a[mi], b[nip][0], b[nip][1]);
                mma16816(acc[mi][2 * nip + 1], a[mi], b[nip][2], b[nip][3]);
            }
    }

    // ---- epilogue: scale x2, mask diag, exp, per-row reduce ----
    int qrow = lane >> 2;          // 0..7
    int qcol = (lane & 3) * 2;
#pragma unroll
    for (int mi = 0; mi < 2; mi++) {
#pragma unroll
        for (int h = 0; h < 2; h++) {
            int row_local = wm * 32 + mi * 16 + qrow + 8 * h;
            int row = row0 + row_local;
            int ridx = row & 2047;
            int half = row >> 11;
            bool tgt = (cblk == 1 - half);
            float sum = 0.f, pos = 0.f;
#pragma unroll
            for (int ni = 0; ni < 8; ni++) {
#pragma unroll
                for (int j = 0; j < 2; j++) {
                    float v = acc[mi][ni][2 * h + j] * 2.0f;   // 1/T = 2
                    int col = col0 + wn * 64 + ni * 8 + qcol + j;
                    float e = __expf(v);
                    if ((col & 2047) == ridx) {                // diagonal entry
                        if (tgt) pos += v;
                        else e = 0.f;                          // masked
                    }
                    sum += e;
                }
            }
            sum += __shfl_xor_sync(~0u, sum, 1);
            sum += __shfl_xor_sync(~0u, sum, 2);
            pos += __shfl_xor_sync(~0u, pos, 1);
            pos += __shfl_xor_sync(~0u, pos, 2);
            if ((lane & 3) == 0) {
                sS[wn * 128 + row_local] = sum;
                sP[wn * 128 + row_local] = pos;
            }
        }
    }
    __syncthreads();

    if (tid < 128) {
        int row = row0 + tid;
        g_S[cs * 4096 + row] = sS[tid] + sS[128 + tid];
        g_pos[cs * 4096 + row] = sP[tid] + sP[128 + tid];
    }
}

// ---------------------------------------------------------------------------
// Kernel 3: loss = mean over 4096 rows of log(sum over 64 coltiles) - pos.
// ---------------------------------------------------------------------------
__global__ void finalize_kernel(float* __restrict__ out) {
    __shared__ float red[1024];
    int tid = threadIdx.x;
    float local = 0.f;
#pragma unroll
    for (int i = 0; i < 4; i++) {
        int row = tid + i * 1024;
        float S = 0.f, p = 0.f;
#pragma unroll
        for (int c = 0; c < 64; c++) {
            S += g_S[c * 4096 + row];
            p += g_pos[c * 4096 + row];
        }
        local += logf(S) - p;
    }
    red[tid] = local;
    __syncthreads();
#pragma unroll
    for (int s = 512; s; s >>= 1) {
        if (tid < s) red[tid] += red[tid + s];
        __syncthreads();
    }
    if (tid == 0) out[0] = red[0] / 4096.f;
}

// ---------------------------------------------------------------------------
extern "C" void kernel_launch(void* const* d_in, const int* in_sizes, int n_in,
                              void* d_out, int out_size) {
    const float* a1 = (const float*)d_in[0];
    const float* a2 = (const float*)d_in[1];
    const float* a3 = (const float*)d_in[2];
    const float* a4 = (const float*)d_in[3];

    normalize_kernel<<<1024, 256>>>(a1, a2, a3, a4);

    cudaFuncSetAttribute(sim_kernel, cudaFuncAttributeMaxDynamicSharedMemorySize,
                         SMEM_BYTES);
    dim3 grid(32, 64);
    sim_kernel<<<grid, 256, SMEM_BYTES>>>();

    finalize_kernel<<<1, 1024>>>((float*)d_out);
}

// round 4
// speedup vs baseline: 7.0100x; 1.1778x over previous
#include <cuda_runtime.h>
#include <cuda_bf16.h>
#include <cstdint>

// Problem: N=2048, D=128, k=4, T=0.5.
// queries rows = 4096, keys cols = 8192.
// sim = norm(z[0:4096]) @ norm(z_all)^T * 2 ; mask non-target diagonals;
// loss = mean(logsumexp - pos). Logits bounded in [-2,2] -> no max needed;
// masked entries contribute exp(-inf)=0 so we just zero them.

#define DIMK 128

// ---------------- device scratch (no allocations allowed) -------------------
__device__ __nv_bfloat16 g_nb[8192 * 128];  // normalized rows, bf16
__device__ float g_S[64 * 4096];            // per (coltile,row) exp-sum
__device__ float g_pos[64 * 4096];          // per (coltile,row) positive logit
__device__ float g_row[4096];               // per-row LSE - pos

__device__ __forceinline__ uint32_t smem_u32(const void* p) {
    uint32_t a;
    asm("{ .reg .u64 t; cvta.to.shared.u64 t, %1; cvt.u32.u64 %0, t; }"
        : "=r"(a) : "l"(p));
    return a;
}

__device__ __forceinline__ void ldsm_x4(uint32_t* r, uint32_t addr) {
    asm volatile("ldmatrix.sync.aligned.m8n8.x4.shared.b16 {%0,%1,%2,%3}, [%4];"
                 : "=r"(r[0]), "=r"(r[1]), "=r"(r[2]), "=r"(r[3]) : "r"(addr));
}

__device__ __forceinline__ void mma16816(float* c, const uint32_t* a,
                                         uint32_t b0, uint32_t b1) {
    asm volatile(
        "mma.sync.aligned.m16n8k16.row.col.f32.bf16.bf16.f32 "
        "{%0,%1,%2,%3}, {%4,%5,%6,%7}, {%8,%9}, {%0,%1,%2,%3};"
        : "+f"(c[0]), "+f"(c[1]), "+f"(c[2]), "+f"(c[3])
        : "r"(a[0]), "r"(a[1]), "r"(a[2]), "r"(a[3]), "r"(b0), "r"(b1));
}

#define CP_ASYNC16(sm, gp) \
    asm volatile("cp.async.cg.shared.global [%0], [%1], 16;" :: "r"(sm), "l"(gp))
#define CP_COMMIT() asm volatile("cp.async.commit_group;" ::: "memory")
#define CP_WAIT_ALL() asm volatile("cp.async.wait_all;" ::: "memory")

// ---------------------------------------------------------------------------
// Kernel 1: L2-normalize 8192 rows -> bf16. One warp per TWO rows (ILP=2).
// grid 512 x 256.
// ---------------------------------------------------------------------------
__global__ void normalize_kernel(const float* __restrict__ a1,
                                 const float* __restrict__ a2,
                                 const float* __restrict__ a3,
                                 const float* __restrict__ a4) {
    int w = threadIdx.x >> 5, lane = threadIdx.x & 31;
    int row0 = blockIdx.x * 16 + w * 2;
    float4 v[2];
    float ss[2];
#pragma unroll
    for (int i = 0; i < 2; i++) {
        int row = row0 + i;
        const float* src = (row < 2048) ? a1 : (row < 4096) ? a2
                          : (row < 6144) ? a3 : a4;
        v[i] = *(const float4*)(src + (row & 2047) * DIMK + lane * 4);
        ss[i] = v[i].x * v[i].x + v[i].y * v[i].y + v[i].z * v[i].z + v[i].w * v[i].w;
    }
#pragma unroll
    for (int off = 16; off; off >>= 1) {
        ss[0] += __shfl_xor_sync(~0u, ss[0], off);
        ss[1] += __shfl_xor_sync(~0u, ss[1], off);
    }
#pragma unroll
    for (int i = 0; i < 2; i++) {
        float inv = 1.0f / fmaxf(sqrtf(ss[i]), 1e-8f);
        __nv_bfloat162 p0 = __float22bfloat162_rn(make_float2(v[i].x * inv, v[i].y * inv));
        __nv_bfloat162 p1 = __float22bfloat162_rn(make_float2(v[i].z * inv, v[i].w * inv));
        uint2 st;
        st.x = *(uint32_t*)&p0;
        st.y = *(uint32_t*)&p1;
        ((uint2*)(g_nb + (row0 + i) * DIMK))[lane] = st;
    }
}

// ---------------------------------------------------------------------------
// Kernel 2: HMMA bf16 GEMM. CTA tile = 128 rows x 512 cols (4 subtiles of
// 128 cols), K=128 in one shot. A loaded once; B double-buffered via
// cp.async prefetch overlapped with compute. 256 threads = 8 warps
// (4 M x 2 N), warp tile 32x64. grid = (32 row tiles, 16 col groups).
// ---------------------------------------------------------------------------
#define TSTRIDE 272                 // bytes per SMEM tile row (128 bf16 + 8 pad)
#define SM_A 0
#define SM_B0 (128 * TSTRIDE)       // 34816
#define SM_B1 (2 * 128 * TSTRIDE)   // 69632
#define SM_S (3 * 128 * TSTRIDE)    // 104448: float sS[2][128]
#define SM_P (SM_S + 1024)
#define SMEM_BYTES (SM_P + 1024)    // 106496

__device__ __forceinline__ void issue_tile_load(char* smem, int sm_off,
                                                int grow0, int tid) {
    uint32_t sb = smem_u32(smem);
#pragma unroll
    for (int it = 0; it < 8; it++) {
        int idx = it * 256 + tid;           // 2048 16B vectors
        int r = idx >> 4, g = idx & 15;
        CP_ASYNC16(sb + sm_off + r * TSTRIDE + g * 16,
                   (const char*)(g_nb + (grow0 + r) * DIMK + g * 8));
    }
}

__global__ void __launch_bounds__(256, 2) sim_kernel() {
    extern __shared__ char smem[];
    uint32_t sb = smem_u32(smem);
    float* sS = (float*)(smem + SM_S);
    float* sP = (float*)(smem + SM_P);

    int tid = threadIdx.x;
    int lane = tid & 31;
    int w = tid >> 5;
    int wm = w & 3;        // M warp (rows wm*32..+31)
    int wn = w >> 2;       // N warp (cols wn*64..+63)
    int row0 = blockIdx.x * 128;
    int cg = blockIdx.y;                  // col group: cols [cg*512, cg*512+512)

    // ---- prologue: A + B0 ----
    issue_tile_load(smem, SM_A, row0, tid);
    issue_tile_load(smem, SM_B0, cg * 512, tid);
    CP_COMMIT();

    // ---- ldmatrix lane address bases ----
    int arow = wm * 32 + ((lane >> 3) & 1) * 8 + (lane & 7);
    int akoct = (lane >> 4) * 8;
    uint32_t baseA = sb + SM_A + arow * TSTRIDE + akoct * 2;
    int brow = wn * 64 + ((lane >> 4) & 1) * 8 + (lane & 7);
    int bkoct = ((lane >> 3) & 1) * 8;
    uint32_t baseBoff = brow * TSTRIDE + bkoct * 2;

    int qrow = lane >> 2;          // 0..7
    int qcol = (lane & 3) * 2;

    for (int ct = 0; ct < 4; ct++) {
        CP_WAIT_ALL();
        __syncthreads();           // B(ct) visible; all warps past iter ct-1

        // prefetch B(ct+1) into the other buffer (overlaps with compute below)
        if (ct < 3) {
            issue_tile_load(smem, ((ct + 1) & 1) ? SM_B1 : SM_B0,
                            cg * 512 + (ct + 1) * 128, tid);
            CP_COMMIT();
        }

        uint32_t baseB = sb + ((ct & 1) ? SM_B1 : SM_B0) + baseBoff;

        float acc[2][8][4];
#pragma unroll
        for (int mi = 0; mi < 2; mi++)
#pragma unroll
            for (int ni = 0; ni < 8; ni++)
#pragma unroll
                for (int c = 0; c < 4; c++) acc[mi][ni][c] = 0.f;

#pragma unroll
        for (int ks = 0; ks < 8; ks++) {
            uint32_t a[2][4];
            ldsm_x4(a[0], baseA + ks * 32);
            ldsm_x4(a[1], baseA + 16 * TSTRIDE + ks * 32);
            uint32_t b[4][4];
#pragma unroll
            for (int nip = 0; nip < 4; nip++)
                ldsm_x4(b[nip], baseB + nip * 16 * TSTRIDE + ks * 32);
#pragma unroll
            for (int mi = 0; mi < 2; mi++)
#pragma unroll
                for (int nip = 0; nip < 4; nip++) {
                    mma16816(acc[mi][2 * nip + 0], a[mi], b[nip][0], b[nip][1]);
                    mma16816(acc[mi][2 * nip + 1], a[mi], b[nip][2], b[nip][3]);
                }
        }

        // ---- epilogue: scale x2, mask diag, exp, per-row reduce ----
        int coltile = cg * 4 + ct;          // 0..63
        int col0 = coltile * 128;
        int cblk = coltile >> 4;            // which 2048-block
#pragma unroll
        for (int mi = 0; mi < 2; mi++) {
#pragma unroll
            for (int h = 0; h < 2; h++) {
                int row_local = wm * 32 + mi * 16 + qrow + 8 * h;
                int row = row0 + row_local;
                int ridx = row & 2047;
                int half = row >> 11;
                bool tgt = (cblk == 1 - half);
                float sum = 0.f, pos = 0.f;
#pragma unroll
                for (int ni = 0; ni < 8; ni++) {
#pragma unroll
                    for (int j = 0; j < 2; j++) {
                        float v = acc[mi][ni][2 * h + j] * 2.0f;   // 1/T = 2
                        int col = col0 + wn * 64 + ni * 8 + qcol + j;
                        float e = __expf(v);
                        if ((col & 2047) == ridx) {                // diagonal
                            if (tgt) pos += v;
                            else e = 0.f;                          // masked
                        }
                        sum += e;
                    }
                }
                sum += __shfl_xor_sync(~0u, sum, 1);
                sum += __shfl_xor_sync(~0u, sum, 2);
                pos += __shfl_xor_sync(~0u, pos, 1);
                pos += __shfl_xor_sync(~0u, pos, 2);
                if ((lane & 3) == 0) {
                    sS[wn * 128 + row_local] = sum;
                    sP[wn * 128 + row_local] = pos;
                }
            }
        }
        __syncthreads();
        if (tid < 128) {
            int row = row0 + tid;
            g_S[coltile * 4096 + row] = sS[tid] + sS[128 + tid];
            g_pos[coltile * 4096 + row] = sP[tid] + sP[128 + tid];
        }
        // next iteration's leading __syncthreads orders sS reuse
    }
}

// ---------------------------------------------------------------------------
// Kernel 3a: per-row LSE - pos over 64 coltile partials. grid 16 x 256.
// ---------------------------------------------------------------------------
__global__ void row_lse_kernel() {
    int row = blockIdx.x * 256 + threadIdx.x;
    float S = 0.f, p = 0.f;
#pragma unroll
    for (int c = 0; c < 64; c++) {
        S += g_S[c * 4096 + row];
        p += g_pos[c * 4096 + row];
    }
    g_row[row] = logf(S) - p;
}

// ---------------------------------------------------------------------------
// Kernel 3b: mean over 4096 rows.
// ---------------------------------------------------------------------------
__global__ void final_sum_kernel(float* __restrict__ out) {
    __shared__ float red[1024];
    int tid = threadIdx.x;
    float local = g_row[tid] + g_row[tid + 1024] + g_row[tid + 2048] + g_row[tid + 3072];
    red[tid] = local;
    __syncthreads();
#pragma unroll
    for (int s = 512; s; s >>= 1) {
        if (tid < s) red[tid] += red[tid + s];
        __syncthreads();
    }
    if (tid == 0) out[0] = red[0] / 4096.f;
}

// ---------------------------------------------------------------------------
extern "C" void kernel_launch(void* const* d_in, const int* in_sizes, int n_in,
                              void* d_out, int out_size) {
    const float* a1 = (const float*)d_in[0];
    const float* a2 = (const float*)d_in[1];
    const float* a3 = (const float*)d_in[2];
    const float* a4 = (const float*)d_in[3];

    normalize_kernel<<<512, 256>>>(a1, a2, a3, a4);

    cudaFuncSetAttribute(sim_kernel, cudaFuncAttributeMaxDynamicSharedMemorySize,
                         SMEM_BYTES);
    dim3 grid(32, 16);
    sim_kernel<<<grid, 256, SMEM_BYTES>>>();

    row_lse_kernel<<<16, 256>>>();
    final_sum_kernel<<<1, 1024>>>((float*)d_out);
}